// round 2
// baseline (speedup 1.0000x reference)
#include <cuda_runtime.h>

// Problem constants (from reference: x shape (4, 32, 256, 256), KS=3)
#define B   4
#define C   32
#define H   256
#define W   256
#define KS  3
#define H3  (H * KS)         // 768
#define W3  (W * KS)         // 768
#define PLANE_IN  (H * W)    // 65536
#define PLANE_OUT (H3 * W3)  // 589824
#define W3Q (W3 / 4)         // 192 float4 per output row
#define TOTAL4 (B * C * H3 * W3Q)   // 18,874,368 float4 outputs

// Deformable conv with zero offsets degenerates to:
//   out[p, I, J] = x[p, reflect(I/3 + I%3 - 1), reflect(J/3 + J%3 - 1)]
//                  * (I==H3-1 ? 2 : 1) * (J==W3-1 ? 2 : 1)
// reflect: -1 -> 1, H -> H-2 (ReflectionPad2d(1) semantics).

__device__ __forceinline__ int reflect_idx(int v, int n) {
    // v in [-1, n]; map -1 -> 1, n -> n-2
    if (v < 0)  return 1;
    if (v >= n) return n - 2;
    return v;
}

__global__ __launch_bounds__(256)
void deform_gather_kernel(const float* __restrict__ x, float* __restrict__ out) {
    int f = blockIdx.x * blockDim.x + threadIdx.x;
    if (f >= TOTAL4) return;

    int Jq    = f % W3Q;          // float4 index within output row
    int t     = f / W3Q;
    int I     = t % H3;           // output row
    int plane = t / H3;           // b*C + c

    // Row mapping (shared by all 4 elements)
    int i  = I / KS;
    int kx = I - i * KS;          // I % 3
    int r  = reflect_idx(i + kx - 1, H);
    float multr = (I == H3 - 1) ? 2.0f : 1.0f;

    const float* __restrict__ row = x + (size_t)plane * PLANE_IN + (size_t)r * W;

    int J0 = Jq * 4;
    float4 v;
    float* vp = reinterpret_cast<float*>(&v);

#pragma unroll
    for (int e = 0; e < 4; ++e) {
        int J  = J0 + e;
        int j  = J / KS;
        int ky = J - j * KS;
        int c  = reflect_idx(j + ky - 1, W);
        float multc = (J == W3 - 1) ? 2.0f : 1.0f;
        vp[e] = __ldg(row + c) * (multr * multc);
    }

    reinterpret_cast<float4*>(out)[f] = v;
}

extern "C" void kernel_launch(void* const* d_in, const int* in_sizes, int n_in,
                              void* d_out, int out_size) {
    const float* x = (const float*)d_in[0];
    float* out = (float*)d_out;
    (void)in_sizes; (void)n_in; (void)out_size;

    const int threads = 256;
    const int blocks = (TOTAL4 + threads - 1) / threads;   // 73728
    deform_gather_kernel<<<blocks, threads>>>(x, out);
}

// round 3
// speedup vs baseline: 1.4176x; 1.4176x over previous
#include <cuda_runtime.h>

#define B   4
#define C   32
#define H   256
#define W   256
#define KS  3
#define H3  (H * KS)          // 768
#define W3  (W * KS)          // 768
#define PLANE_IN  (H * W)     // 65536
#define PLANE_OUT (H3 * W3)   // 589824
#define W3Q (W3 / 4)          // 192

// smem layout: 3 input rows, column c stored at index c+4 (4-float front halo
// keeps float4 staging stores 16B-aligned). Indices used: 3 .. 260.
#define SMROW 268

// Per-e packed (d+4) bytes for m=0,1,2 where d = col - 4q:
//   d(m,e): m=0:{-1,0,1,0}  m=1:{1,2,1,2}  m=2:{3,2,3,4}
__device__ __constant__ unsigned int D_TAB[4] = {
    0x00070503u,  // e=0: {3,5,7}
    0x00060604u,  // e=1: {4,6,6}
    0x00070505u,  // e=2: {5,5,7}
    0x00080604u   // e=3: {4,6,8}
};

__global__ __launch_bounds__(192)
void deform_rows_kernel(const float* __restrict__ x, float* __restrict__ out) {
    __shared__ float sm[3][SMROW];

    const int i     = blockIdx.x;            // input row group, 0..255
    const int plane = blockIdx.y;            // b*C + c, 0..127
    const int m     = threadIdx.x;           // 0..2
    const int q     = threadIdx.y;           // 0..63
    const int tid   = m + 3 * q;             // 0..191 == output float4 index

    const float* __restrict__ xp = x + (size_t)plane * PLANE_IN;

    // ---- stage 3 input rows (reflected) with reflected column halo ----
    {
        const int s  = tid >> 6;             // 0..2
        const int c4 = tid & 63;             // 0..63
        int ri = i - 1 + s;
        ri = (ri < 0) ? 1 : ((ri >= H) ? H - 2 : ri);
        const float4 v = reinterpret_cast<const float4*>(xp + ri * W)[c4];
        float* dstp = &sm[s][4 * c4 + 4];
        dstp[0] = v.x; dstp[1] = v.y; dstp[2] = v.z; dstp[3] = v.w;
        if (c4 == 0) {
            // halo: col -1 -> x[1] (idx 3), col 256 -> x[254] (idx 260)
            sm[s][3]   = xp[ri * W + 1];
            sm[s][260] = xp[ri * W + W - 2];
        }
    }
    __syncthreads();

    // ---- column smem indices (shared across the 3 output rows) ----
    const int sh   = 8 * m;
    const int base = 4 * q;
    int ci[4];
#pragma unroll
    for (int e = 0; e < 4; ++e)
        ci[e] = base + (int)((D_TAB[e] >> sh) & 0xFFu);

    const bool  lastJ  = (tid == 191);              // J = 767 -> col weight 2
    const float roww2  = (i == H - 1) ? 2.0f : 1.0f; // row I=767 weight

    float* __restrict__ op = out + (size_t)plane * PLANE_OUT + (size_t)(3 * i) * W3;

#pragma unroll
    for (int kx = 0; kx < 3; ++kx) {
        const float mr = (kx == 2) ? roww2 : 1.0f;
        float4 v;
        v.x = sm[kx][ci[0]] * mr;
        v.y = sm[kx][ci[1]] * mr;
        v.z = sm[kx][ci[2]] * mr;
        v.w = sm[kx][ci[3]] * mr;
        if (lastJ) v.w *= 2.0f;
        reinterpret_cast<float4*>(op + (size_t)kx * W3)[tid] = v;
    }
}

extern "C" void kernel_launch(void* const* d_in, const int* in_sizes, int n_in,
                              void* d_out, int out_size) {
    const float* x = (const float*)d_in[0];
    float* out = (float*)d_out;
    (void)in_sizes; (void)n_in; (void)out_size;

    dim3 grid(H, B * C);        // 256 x 128
    dim3 block(3, 64);          // 192 threads
    deform_rows_kernel<<<grid, block>>>(x, out);
}

// round 4
// speedup vs baseline: 1.4198x; 1.0016x over previous
#include <cuda_runtime.h>

#define B 4
#define C 32
#define H 256
#define W 256
#define H3 768
#define W3 768
#define PLANE_IN  65536
#define PLANE_OUT 589824
// skewed smem row: max skewed index = skew(260) = 268 -> pad to 272
#define SMROW 272

__device__ __forceinline__ int skew(int i) { return i + (i >> 5); }

// out[p, I, J] = x[p, reflect(I/3 + I%3 - 1), reflect(J/3 + J%3 - 1)]
//                * (I==767 ? 2 : 1) * (J==767 ? 2 : 1)
// Block: 2 row-groups (i2, i2+1): stages input rows i2-1..i2+2 (reflected,
// with column halo baked in), writes 6 output rows of 768 floats each.
__global__ __launch_bounds__(384)
void deform2_kernel(const float* __restrict__ x, float* __restrict__ out) {
    __shared__ float sm[4][SMROW];

    const int tid   = threadIdx.x;
    const int i2    = blockIdx.x * 2;      // input row group base (0..254, even)
    const int plane = blockIdx.y;          // b*C + c

    const float* __restrict__ xp = x + (size_t)plane * PLANE_IN;

    // ---- stage 4 reflected input rows, skewed layout, col c at idx c+4 ----
    if (tid < 256) {
        const int s  = tid >> 6;           // 0..3 smem row
        const int c4 = tid & 63;           // float4 column
        int ri = i2 - 1 + s;
        ri = (ri < 0) ? 1 : ((ri > H - 1) ? H - 2 : ri);
        const float4 v = reinterpret_cast<const float4*>(xp + ri * W)[c4];
        float* r = sm[s];
        const int b0 = 4 * c4 + 4;
        r[skew(b0)]     = v.x;
        r[skew(b0 + 1)] = v.y;
        r[skew(b0 + 2)] = v.z;
        r[skew(b0 + 3)] = v.w;
        if (c4 == 0)  r[3]   = v.y;        // skew(3)==3:  col -1 -> x[1]
        if (c4 == 63) r[268] = v.z;        // skew(260):   col 256 -> x[254]
    }
    __syncthreads();

    // ---- compute: thread = (grp, t); t = output float4 index in row ----
    const int grp = (tid >= 192) ? 1 : 0;
    const int t   = tid - 192 * grp;       // 0..191
    const int m   = t % 3;
    const int q   = t / 3;
    const int ig  = i2 + grp;              // input row group 0..255

    // distinct column idx offsets for this m (see derivation):
    //   m=0: {3,4,5}  m=1: {5,6,6}  m=2: {7,6,8}
    const int d0 = 3 + 2 * m;
    const int d1 = m ? 6 : 4;
    const int d2 = 5 + m + (m >> 1);
    const int s0 = skew(4 * q + d0);
    const int s1 = skew(4 * q + d1);
    const int s2 = skew(4 * q + d2);
    const bool m0    = (m == 0);
    const bool m2    = (m == 2);
    const bool lastv = (t == 191);         // J = 767 lives in this thread's .w

    float4* __restrict__ op = reinterpret_cast<float4*>(
        out + (size_t)plane * PLANE_OUT + (size_t)(3 * ig) * W3) + t;

#pragma unroll
    for (int kx = 0; kx < 3; ++kx) {
        const float* r = sm[grp + kx];
        const float L0 = r[s0];
        const float L1 = r[s1];
        const float L2 = r[s2];
        float4 v;
        v.x = L0;
        v.y = L1;
        v.z = m0 ? L2 : L0;
        v.w = m2 ? L2 : L1;
        if (kx == 2 && ig == H - 1) {      // output row I=767: weight 2 (uniform)
            v.x *= 2.0f; v.y *= 2.0f; v.z *= 2.0f; v.w *= 2.0f;
        }
        if (lastv) v.w *= 2.0f;            // output col J=767: weight 2
        op[kx * (W3 / 4)] = v;
    }
}

extern "C" void kernel_launch(void* const* d_in, const int* in_sizes, int n_in,
                              void* d_out, int out_size) {
    const float* x = (const float*)d_in[0];
    float* out = (float*)d_out;
    (void)in_sizes; (void)n_in; (void)out_size;

    dim3 grid(H / 2, B * C);    // 128 x 128
    deform2_kernel<<<grid, 384>>>(x, out);
}

// round 5
// speedup vs baseline: 1.5212x; 1.0714x over previous
#include <cuda_runtime.h>

#define B 4
#define C 32
#define H 256
#define W 256
#define H3 768
#define W3 768
#define PLANE_IN  65536
#define PLANE_OUT 589824
#define SMROW 272              // skewed row: skew(260)=268 -> pad 272
#define STRIP 8                // input row-groups per block
#define SROWS (STRIP + 2)      // 10 staged input rows
#define NTHR 384

__device__ __forceinline__ int skew(int i) { return i + (i >> 5); }

// out[p, I, J] = x[p, reflect(I/3+I%3-1), reflect(J/3+J%3-1)]
//                * (I==767?2:1) * (J==767?2:1)
__global__ __launch_bounds__(NTHR)
void deform_strip_kernel(const float* __restrict__ x, float* __restrict__ out) {
    __shared__ float sm[SROWS][SMROW];

    const int tid   = threadIdx.x;
    const int base  = blockIdx.x * STRIP;   // first input row-group of strip
    const int plane = blockIdx.y;           // b*C + c

    const float* __restrict__ xp = x + (size_t)plane * PLANE_IN;

    // ---- stage SROWS reflected input rows (single pass, MLP=2) ----
#pragma unroll
    for (int k = 0; k < 2; ++k) {
        const int idx = tid + NTHR * k;     // 0..767; need < SROWS*64 = 640
        if (idx < SROWS * 64) {
            const int s  = idx >> 6;        // smem row 0..9
            const int c4 = idx & 63;        // float4 col
            int ri = base - 1 + s;
            ri = (ri < 0) ? 1 : ((ri > H - 1) ? H - 2 : ri);
            const float4 v = reinterpret_cast<const float4*>(xp + ri * W)[c4];
            float* r = sm[s];
            const int b0 = 4 * c4 + 4;
            r[skew(b0)]     = v.x;
            r[skew(b0 + 1)] = v.y;
            r[skew(b0 + 2)] = v.z;
            r[skew(b0 + 3)] = v.w;
            if (c4 == 0)  r[3]   = v.y;     // col -1 -> x[1]   (skew(3)==3)
            if (c4 == 63) r[268] = v.z;     // col 256 -> x[254] (skew(260))
        }
    }
    __syncthreads();

    // ---- compute: (grp, t); t = output float4 index within a row ----
    const int grp = (tid >= 192) ? 1 : 0;
    const int t   = tid - 192 * grp;        // 0..191
    const int m   = t % 3;
    const int q   = t / 3;

    // distinct column idx offsets per m:  m=0:{3,4,5} m=1:{5,6,6} m=2:{7,6,8}
    const int d0 = 3 + 2 * m;
    const int d1 = m ? 6 : 4;
    const int d2 = 5 + m + (m >> 1);
    const int s0 = skew(4 * q + d0);
    const int s1 = skew(4 * q + d1);
    const int s2 = skew(4 * q + d2);
    const bool m0    = (m == 0);
    const bool m2    = (m == 2);
    const bool lastv = (t == 191);          // J=767 lives in .w of this thread

    float* __restrict__ opl = out + (size_t)plane * PLANE_OUT;

#pragma unroll
    for (int g = 0; g < STRIP / 2; ++g) {
        const int gl = 2 * g + grp;         // local group 0..7
        const int ig = base + gl;           // global input row group
        float4* __restrict__ op =
            reinterpret_cast<float4*>(opl + (size_t)(3 * ig) * W3) + t;
        const bool lastrow = (ig == H - 1);

#pragma unroll
        for (int kx = 0; kx < 3; ++kx) {
            const float* r = sm[gl + kx];   // input rows ig-1..ig+1
            const float L0 = r[s0];
            const float L1 = r[s1];
            const float L2 = r[s2];
            float4 v;
            v.x = L0;
            v.y = L1;
            v.z = m0 ? L2 : L0;
            v.w = m2 ? L2 : L1;
            if (kx == 2 && lastrow) {       // output row I=767 weight 2
                v.x *= 2.0f; v.y *= 2.0f; v.z *= 2.0f; v.w *= 2.0f;
            }
            if (lastv) v.w *= 2.0f;         // output col J=767 weight 2
            op[kx * (W3 / 4)] = v;
        }
    }
}

extern "C" void kernel_launch(void* const* d_in, const int* in_sizes, int n_in,
                              void* d_out, int out_size) {
    const float* x = (const float*)d_in[0];
    float* out = (float*)d_out;
    (void)in_sizes; (void)n_in; (void)out_size;

    dim3 grid(H / STRIP, B * C);   // 32 x 128 = 4096 blocks
    deform_strip_kernel<<<grid, NTHR>>>(x, out);
}